// round 1
// baseline (speedup 1.0000x reference)
#include <cuda_runtime.h>
#include <math.h>
#include <float.h>

// RobustCombiner: B=4, S=512, K=32, MID=32, V=32000
// Inputs (metadata order):
//  0 tgt_index            int32  [B,S,K]
//  1 knn_dists            f32    [B,S,K]
//  2 knn_key_feature      f32    [B,S,K]
//  3 network_probs        f32    [B,S,V]
//  4 network_select_probs f32    [B,S,K]
//  5 W_func f32 [1,72]   6 b_func f32 [1]
//  7 W1a    f32 [4,2]    8 b1a    f32 [4]
//  9 W1b    f32 [1,4]   10 b1b    f32 [1]
// 11 W2a    f32 [32,64] 12 b2a    f32 [32]
// 13 W2b    f32 [2,32]  14 b2b    f32 [2]
// Output: concat( knn_prob [B,S,V], knn_lambda [B,S,1] ) as f32.

#define KNN 32
#define TPB 256

__device__ __forceinline__ void ins8(float t[8], float v) {
    if (v <= t[7]) return;
    t[7] = v;
#pragma unroll
    for (int i = 7; i > 0; --i) {
        if (t[i] > t[i - 1]) { float tmp = t[i - 1]; t[i - 1] = t[i]; t[i] = tmp; }
    }
}

__global__ __launch_bounds__(TPB) void combiner_kernel(
    const int*   __restrict__ tgt_index,
    const float* __restrict__ knn_dists,
    const float* __restrict__ knn_key,
    const float* __restrict__ net_probs,
    const float* __restrict__ net_sel,
    const float* __restrict__ W_func, const float* __restrict__ b_func,
    const float* __restrict__ W1a,    const float* __restrict__ b1a,
    const float* __restrict__ W1b,    const float* __restrict__ b1b,
    const float* __restrict__ W2a,    const float* __restrict__ b2a,
    const float* __restrict__ W2b,    const float* __restrict__ b2b,
    float* __restrict__ out, int V, int rows)
{
    const int row = blockIdx.x;
    const int tid = threadIdx.x;

    __shared__ float sW2a[32 * 64];     // 8 KB
    __shared__ float sTop[TPB * 8];     // 8 KB merge workspace
    __shared__ int   sLab[KNN];
    __shared__ float sP[KNN];

    // Stage W2a (reused 32x64 dot per row) into shared.
    for (int i = tid; i < 32 * 64; i += TPB) sW2a[i] = W2a[i];

    // ---- Stream the probs row: fused (read -> local top-8) + (write zeros) ----
    const float* prow = net_probs + (size_t)row * V;
    float*       orow = out       + (size_t)row * V;

    float t[8];
#pragma unroll
    for (int i = 0; i < 8; ++i) t[i] = -FLT_MAX;

    if ((V & 3) == 0) {
        const float4* pr4 = reinterpret_cast<const float4*>(prow);
        float4*       or4 = reinterpret_cast<float4*>(orow);
        const int n4 = V >> 2;
        const float4 z = make_float4(0.f, 0.f, 0.f, 0.f);
        for (int i = tid; i < n4; i += TPB) {
            float4 v = __ldcs(&pr4[i]);
            ins8(t, v.x); ins8(t, v.y); ins8(t, v.z); ins8(t, v.w);
            __stcs(&or4[i], z);
        }
    } else {
        for (int i = tid; i < V; i += TPB) {
            float v = __ldcs(&prow[i]);
            ins8(t, v);
            __stcs(&orow[i], 0.f);
        }
    }

    // ---- Block-wide top-8 merge (sorted-descending 8-lists, two-pointer) ----
#pragma unroll
    for (int i = 0; i < 8; ++i) sTop[tid * 8 + i] = t[i];
    __syncthreads();

    for (int stride = TPB / 2; stride >= 1; stride >>= 1) {
        if (tid < stride) {
            float a[8], b[8], r[8];
#pragma unroll
            for (int i = 0; i < 8; ++i) { a[i] = sTop[tid * 8 + i]; b[i] = sTop[(tid + stride) * 8 + i]; }
            int ia = 0, ib = 0;
#pragma unroll
            for (int i = 0; i < 8; ++i) {
                if (a[ia] >= b[ib]) r[i] = a[ia++];
                else                r[i] = b[ib++];
            }
#pragma unroll
            for (int i = 0; i < 8; ++i) sTop[tid * 8 + i] = r[i];
        }
        __syncthreads();
    }
    // sTop[0..7] = top-8 descending for this row.

    // ---- Per-row scalar math: warp 0 only ----
    if (tid < 32) {
        const unsigned full = 0xffffffffu;
        const int lane = tid;
        const size_t kbase = (size_t)row * KNN;

        const int   lab = tgt_index[kbase + lane];
        const float d   = knn_dists[kbase + lane];
        const float lk  = logf(knn_key[kbase + lane]);
        const float ls  = logf(net_sel[kbase + lane]);

        // label_counts: # distinct NONZERO labels among prefix [0..lane]
        int fo = (lab != 0) ? 1 : 0;
#pragma unroll
        for (int i = 0; i < 31; ++i) {
            int li = __shfl_sync(full, lab, i);
            if (i < lane && li == lab) fo = 0;
        }
        int cnt = fo;
#pragma unroll
        for (int off = 1; off < 32; off <<= 1) {
            int n = __shfl_up_sync(full, cnt, off);
            if (lane >= off) cnt += n;
        }
        const float cntf = (float)cnt;

        // noise_logit: Linear(2,4)->tanh->Linear(4,1) on [lk, ls]
        float nl = b1b[0];
#pragma unroll
        for (int m = 0; m < 4; ++m) {
            float h = tanhf(fmaf(W1a[2 * m], lk, fmaf(W1a[2 * m + 1], ls, b1a[m])));
            nl = fmaf(W1b[m], h, nl);
        }

        // sim_lambda = W_func . [log(top8), lk(32), ls(32)] + b_func  (warp reduce)
        float sc = fmaf(W_func[8 + lane], lk, W_func[40 + lane] * ls);
        if (lane < 8) sc = fmaf(W_func[lane], logf(sTop[lane]), sc);
        float sl = sc;
#pragma unroll
        for (int off = 16; off >= 1; off >>= 1) sl += __shfl_xor_sync(full, sl, off);
        sl += b_func[0];

        // lambda_logit: Linear(64,32)->tanh->Linear(32,2) on [dists(32), counts(32)]
        float acc = b2a[lane];
#pragma unroll
        for (int j = 0; j < 32; ++j) {
            float dj = __shfl_sync(full, d, j);
            float cj = __shfl_sync(full, cntf, j);
            acc = fmaf(sW2a[lane * 64 + j], dj, acc);
            acc = fmaf(sW2a[lane * 64 + 32 + j], cj, acc);
        }
        float h = tanhf(acc);
        float c0 = W2b[lane] * h;
        float c1 = W2b[32 + lane] * h;
#pragma unroll
        for (int off = 16; off >= 1; off >>= 1) {
            c0 += __shfl_xor_sync(full, c0, off);
            c1 += __shfl_xor_sync(full, c1, off);
        }
        const float l0 = c0 + b2b[0];
        const float l1 = c1 + b2b[1];

        // softmax([l0, sl])[0] = sigmoid(l0 - sl)
        const float knn_lambda = 1.f / (1.f + expf(sl - l0));
        const float tempe      = 1.f / (1.f + expf(-l1));

        // probs = softmax_k(-d * tempe + nl)
        float logit = fmaf(-d, tempe, nl);
        float mx = logit;
#pragma unroll
        for (int off = 16; off >= 1; off >>= 1) mx = fmaxf(mx, __shfl_xor_sync(full, mx, off));
        float e = expf(logit - mx);
        float se = e;
#pragma unroll
        for (int off = 16; off >= 1; off >>= 1) se += __shfl_xor_sync(full, se, off);
        const float p = e / se;

        sLab[lane] = lab;
        sP[lane]   = p;
        __syncwarp();

        if (lane == 0) {
            // serial scatter: last write wins on duplicate indices
#pragma unroll 4
            for (int k = 0; k < KNN; ++k) orow[sLab[k]] = sP[k];
            out[(size_t)rows * V + row] = knn_lambda;
        }
    }
}

extern "C" void kernel_launch(void* const* d_in, const int* in_sizes, int n_in,
                              void* d_out, int out_size) {
    const int*   tgt_index = (const int*)  d_in[0];
    const float* knn_dists = (const float*)d_in[1];
    const float* knn_key   = (const float*)d_in[2];
    const float* net_probs = (const float*)d_in[3];
    const float* net_sel   = (const float*)d_in[4];
    const float* W_func = (const float*)d_in[5];
    const float* b_func = (const float*)d_in[6];
    const float* W1a    = (const float*)d_in[7];
    const float* b1a    = (const float*)d_in[8];
    const float* W1b    = (const float*)d_in[9];
    const float* b1b    = (const float*)d_in[10];
    const float* W2a    = (const float*)d_in[11];
    const float* b2a    = (const float*)d_in[12];
    const float* W2b    = (const float*)d_in[13];
    const float* b2b    = (const float*)d_in[14];

    const int rows = in_sizes[0] / KNN;          // B*S = 2048
    const int V    = in_sizes[3] / rows;         // 32000

    combiner_kernel<<<rows, TPB>>>(
        tgt_index, knn_dists, knn_key, net_probs, net_sel,
        W_func, b_func, W1a, b1a, W1b, b1b, W2a, b2a, W2b, b2b,
        (float*)d_out, V, rows);
}

// round 2
// speedup vs baseline: 1.0674x; 1.0674x over previous
#include <cuda_runtime.h>
#include <math.h>
#include <float.h>

// RobustCombiner: B=4, S=512, K=32, MID=32, V=32000
// Output: concat( knn_prob [B,S,V], knn_lambda [B,S,1] ) as f32.

#define KNN 32
#define TPB 256
#define UNROLL 4

__device__ __forceinline__ void ins8(float t[8], float v) {
    if (v <= t[7]) return;
    t[7] = v;
#pragma unroll
    for (int i = 7; i > 0; --i) {
        if (t[i] > t[i - 1]) { float tmp = t[i - 1]; t[i - 1] = t[i]; t[i] = tmp; }
    }
}

__device__ __forceinline__ void check4(float t[8], float4 v) {
    float mx = fmaxf(fmaxf(v.x, v.y), fmaxf(v.z, v.w));
    if (mx > t[7]) {
        ins8(t, v.x); ins8(t, v.y); ins8(t, v.z); ins8(t, v.w);
    }
}

__global__ __launch_bounds__(TPB) void combiner_kernel(
    const int*   __restrict__ tgt_index,
    const float* __restrict__ knn_dists,
    const float* __restrict__ knn_key,
    const float* __restrict__ net_probs,
    const float* __restrict__ net_sel,
    const float* __restrict__ W_func, const float* __restrict__ b_func,
    const float* __restrict__ W1a,    const float* __restrict__ b1a,
    const float* __restrict__ W1b,    const float* __restrict__ b1b,
    const float* __restrict__ W2a,    const float* __restrict__ b2a,
    const float* __restrict__ W2b,    const float* __restrict__ b2b,
    float* __restrict__ out, int V, int rows)
{
    const int row = blockIdx.x;
    const int tid = threadIdx.x;

    __shared__ float sW2a[32 * 64];     // 8 KB
    __shared__ float sTop[TPB * 8];     // 8 KB merge workspace
    __shared__ int   sLab[KNN];
    __shared__ float sP[KNN];

    for (int i = tid; i < 32 * 64; i += TPB) sW2a[i] = W2a[i];

    // ---- Stream the probs row: fused (read -> top-8) + (write zeros) ----
    // Front-batched independent loads (MLP=4), compute, then batched stores.
    const float* prow = net_probs + (size_t)row * V;
    float*       orow = out       + (size_t)row * V;

    float t[8];
#pragma unroll
    for (int i = 0; i < 8; ++i) t[i] = -FLT_MAX;

    const float4* pr4 = reinterpret_cast<const float4*>(prow);
    float4*       or4 = reinterpret_cast<float4*>(orow);
    const int n4 = V >> 2;                       // 8000
    const int nfull = (n4 / (TPB * UNROLL)) * (TPB * UNROLL);  // 7168
    const float4 z = make_float4(0.f, 0.f, 0.f, 0.f);

    for (int i = tid; i < nfull; i += TPB * UNROLL) {
        float4 v0 = __ldcs(&pr4[i]);
        float4 v1 = __ldcs(&pr4[i +     TPB]);
        float4 v2 = __ldcs(&pr4[i + 2 * TPB]);
        float4 v3 = __ldcs(&pr4[i + 3 * TPB]);
        check4(t, v0); check4(t, v1); check4(t, v2); check4(t, v3);
        __stcs(&or4[i],           z);
        __stcs(&or4[i +     TPB], z);
        __stcs(&or4[i + 2 * TPB], z);
        __stcs(&or4[i + 3 * TPB], z);
    }
    // tail (832 float4s), still coalesced
    for (int i = nfull + tid; i < n4; i += TPB) {
        float4 v = __ldcs(&pr4[i]);
        check4(t, v);
        __stcs(&or4[i], z);
    }
    // scalar tail if V not /4 (not hit for V=32000)
    for (int i = (n4 << 2) + tid; i < V; i += TPB) {
        float v = __ldcs(&prow[i]);
        ins8(t, v);
        __stcs(&orow[i], 0.f);
    }

    // ---- Block-wide top-8 merge (sorted-descending 8-lists, two-pointer) ----
#pragma unroll
    for (int i = 0; i < 8; ++i) sTop[tid * 8 + i] = t[i];
    __syncthreads();

    for (int stride = TPB / 2; stride >= 1; stride >>= 1) {
        if (tid < stride) {
            float a[8], b[8], r[8];
#pragma unroll
            for (int i = 0; i < 8; ++i) { a[i] = sTop[tid * 8 + i]; b[i] = sTop[(tid + stride) * 8 + i]; }
            int ia = 0, ib = 0;
#pragma unroll
            for (int i = 0; i < 8; ++i) {
                if (a[ia] >= b[ib]) r[i] = a[ia++];
                else                r[i] = b[ib++];
            }
#pragma unroll
            for (int i = 0; i < 8; ++i) sTop[tid * 8 + i] = r[i];
        }
        __syncthreads();
    }
    // sTop[0..7] = top-8 descending for this row.

    // ---- Per-row scalar math: warp 0 only ----
    if (tid < 32) {
        const unsigned full = 0xffffffffu;
        const int lane = tid;
        const size_t kbase = (size_t)row * KNN;

        const int   lab = tgt_index[kbase + lane];
        const float d   = knn_dists[kbase + lane];
        const float lk  = logf(knn_key[kbase + lane]);
        const float ls  = logf(net_sel[kbase + lane]);

        // label_counts: # distinct NONZERO labels among prefix [0..lane]
        int fo = (lab != 0) ? 1 : 0;
#pragma unroll
        for (int i = 0; i < 31; ++i) {
            int li = __shfl_sync(full, lab, i);
            if (i < lane && li == lab) fo = 0;
        }
        int cnt = fo;
#pragma unroll
        for (int off = 1; off < 32; off <<= 1) {
            int n = __shfl_up_sync(full, cnt, off);
            if (lane >= off) cnt += n;
        }
        const float cntf = (float)cnt;

        // noise_logit: Linear(2,4)->tanh->Linear(4,1) on [lk, ls]
        float nl = b1b[0];
#pragma unroll
        for (int m = 0; m < 4; ++m) {
            float h = tanhf(fmaf(W1a[2 * m], lk, fmaf(W1a[2 * m + 1], ls, b1a[m])));
            nl = fmaf(W1b[m], h, nl);
        }

        // sim_lambda = W_func . [log(top8), lk(32), ls(32)] + b_func
        float sc = fmaf(W_func[8 + lane], lk, W_func[40 + lane] * ls);
        if (lane < 8) sc = fmaf(W_func[lane], logf(sTop[lane]), sc);
        float sl = sc;
#pragma unroll
        for (int off = 16; off >= 1; off >>= 1) sl += __shfl_xor_sync(full, sl, off);
        sl += b_func[0];

        // lambda_logit: Linear(64,32)->tanh->Linear(32,2) on [dists(32), counts(32)]
        float acc = b2a[lane];
#pragma unroll
        for (int j = 0; j < 32; ++j) {
            float dj = __shfl_sync(full, d, j);
            float cj = __shfl_sync(full, cntf, j);
            acc = fmaf(sW2a[lane * 64 + j], dj, acc);
            acc = fmaf(sW2a[lane * 64 + 32 + j], cj, acc);
        }
        float h = tanhf(acc);
        float c0 = W2b[lane] * h;
        float c1 = W2b[32 + lane] * h;
#pragma unroll
        for (int off = 16; off >= 1; off >>= 1) {
            c0 += __shfl_xor_sync(full, c0, off);
            c1 += __shfl_xor_sync(full, c1, off);
        }
        const float l0 = c0 + b2b[0];
        const float l1 = c1 + b2b[1];

        // softmax([l0, sl])[0] = sigmoid(l0 - sl)
        const float knn_lambda = 1.f / (1.f + expf(sl - l0));
        const float tempe      = 1.f / (1.f + expf(-l1));

        // probs = softmax_k(-d * tempe + nl)
        float logit = fmaf(-d, tempe, nl);
        float mx = logit;
#pragma unroll
        for (int off = 16; off >= 1; off >>= 1) mx = fmaxf(mx, __shfl_xor_sync(full, mx, off));
        float e = expf(logit - mx);
        float se = e;
#pragma unroll
        for (int off = 16; off >= 1; off >>= 1) se += __shfl_xor_sync(full, se, off);
        const float p = e / se;

        sLab[lane] = lab;
        sP[lane]   = p;
        __syncwarp();

        if (lane == 0) {
            // serial scatter: last write wins on duplicate indices
#pragma unroll 4
            for (int k = 0; k < KNN; ++k) orow[sLab[k]] = sP[k];
            out[(size_t)rows * V + row] = knn_lambda;
        }
    }
}

extern "C" void kernel_launch(void* const* d_in, const int* in_sizes, int n_in,
                              void* d_out, int out_size) {
    const int*   tgt_index = (const int*)  d_in[0];
    const float* knn_dists = (const float*)d_in[1];
    const float* knn_key   = (const float*)d_in[2];
    const float* net_probs = (const float*)d_in[3];
    const float* net_sel   = (const float*)d_in[4];
    const float* W_func = (const float*)d_in[5];
    const float* b_func = (const float*)d_in[6];
    const float* W1a    = (const float*)d_in[7];
    const float* b1a    = (const float*)d_in[8];
    const float* W1b    = (const float*)d_in[9];
    const float* b1b    = (const float*)d_in[10];
    const float* W2a    = (const float*)d_in[11];
    const float* b2a    = (const float*)d_in[12];
    const float* W2b    = (const float*)d_in[13];
    const float* b2b    = (const float*)d_in[14];

    const int rows = in_sizes[0] / KNN;          // B*S = 2048
    const int V    = in_sizes[3] / rows;         // 32000

    combiner_kernel<<<rows, TPB>>>(
        tgt_index, knn_dists, knn_key, net_probs, net_sel,
        W_func, b_func, W1a, b1a, W1b, b1b, W2a, b2a, W2b, b2b,
        (float*)d_out, V, rows);
}